// round 2
// baseline (speedup 1.0000x reference)
#include <cuda_runtime.h>
#include <math.h>

// Problem constants: B=2, T=2048, D=1024, H=16, HD=64, FF=4096
#define NROWS 4096            // B*T
#define DMODEL 1024
#define NHEAD 16
#define HDIM 64
#define SEQ 2048
#define FFDIM 4096

// ---------------- scratch (static device globals; no allocation) ----------------
__device__ float g_h  [(size_t)NROWS * DMODEL];            // 16 MB  (LN output, reused)
__device__ float g_qkv[(size_t)NROWS * 3 * DMODEL];        // 48 MB
__device__ float g_sc [(size_t)2 * NHEAD * SEQ * SEQ];     // 512 MB (attention scores)
__device__ float g_y  [(size_t)NROWS * DMODEL];            // 16 MB  (attention out)
__device__ float g_x1 [(size_t)NROWS * DMODEL];            // 16 MB  (residual 1)
__device__ float g_ff [(size_t)NROWS * FFDIM];             // 64 MB  (gelu(fc1))

// ---------------- LayerNorm: one block per row of 1024 ----------------
__global__ void ln_k(const float* __restrict__ x, const float* __restrict__ g,
                     const float* __restrict__ b, float* __restrict__ out) {
    __shared__ float red[256];
    const long row = blockIdx.x;
    const float* xr = x + row * (long)DMODEL;
    const int tid = threadIdx.x;
    float v[4];
    float s = 0.f, s2 = 0.f;
#pragma unroll
    for (int i = 0; i < 4; i++) {
        v[i] = xr[tid + i * 256];
        s += v[i];
        s2 += v[i] * v[i];
    }
    red[tid] = s; __syncthreads();
    for (int o = 128; o > 0; o >>= 1) { if (tid < o) red[tid] += red[tid + o]; __syncthreads(); }
    const float mean = red[0] * (1.f / DMODEL);
    __syncthreads();
    red[tid] = s2; __syncthreads();
    for (int o = 128; o > 0; o >>= 1) { if (tid < o) red[tid] += red[tid + o]; __syncthreads(); }
    const float var = red[0] * (1.f / DMODEL) - mean * mean;
    const float inv = rsqrtf(var + 1e-5f);
#pragma unroll
    for (int i = 0; i < 4; i++) {
        const int c = tid + i * 256;
        out[row * (long)DMODEL + c] = (v[i] - mean) * inv * g[c] + b[c];
    }
}

// ---------------- Softmax over rows of length 2048 ----------------
__global__ void softmax_k(float* __restrict__ s) {
    __shared__ float red[256];
    const long row = blockIdx.x;
    float* p = s + row * (long)SEQ;
    const int tid = threadIdx.x;
    float v[8];
    float m = -1e30f;
#pragma unroll
    for (int i = 0; i < 8; i++) { v[i] = p[tid + i * 256]; m = fmaxf(m, v[i]); }
    red[tid] = m; __syncthreads();
    for (int o = 128; o > 0; o >>= 1) { if (tid < o) red[tid] = fmaxf(red[tid], red[tid + o]); __syncthreads(); }
    m = red[0]; __syncthreads();
    float sum = 0.f;
#pragma unroll
    for (int i = 0; i < 8; i++) { v[i] = __expf(v[i] - m); sum += v[i]; }
    red[tid] = sum; __syncthreads();
    for (int o = 128; o > 0; o >>= 1) { if (tid < o) red[tid] += red[tid + o]; __syncthreads(); }
    const float inv = 1.f / red[0];
#pragma unroll
    for (int i = 0; i < 8; i++) p[tid + i * 256] = v[i] * inv;
}

// ---------------- Generic tiled SGEMM with batched offsets + fused epilogue ----
// C[z] = alpha * A[z] @ B[z] (+ bias) (+ gelu) (+ res)
// Batch offset for pointer P: (z / batchH) * sPb + (z % batchH) * sPh
// TRANSB: B element (k, n) read as B[n * ldb + k]
template<int BM, int BN, int BK, int TM, int TN, bool TRANSB, bool GELU>
__global__ __launch_bounds__((BM / TM) * (BN / TN))
void gemm_k(const float* __restrict__ A, const float* __restrict__ B,
            const float* __restrict__ bias, const float* __restrict__ res,
            float* __restrict__ C, int K,
            long lda, long ldb, long ldc,
            int batchH, long sAb, long sAh, long sBb, long sBh, long sCb, long sCh,
            float alpha)
{
    constexpr int THREADS = (BM / TM) * (BN / TN);
    constexpr int KV = BK / 4;   // float4 chunks along k
    __shared__ __align__(16) float As[BK][BM];
    __shared__ __align__(16) float Bs[BK][BN];

    const int z  = blockIdx.z;
    const int zb = z / batchH, zh = z % batchH;
    const float* Ab = A + (long)zb * sAb + (long)zh * sAh;
    const float* Bb = B + (long)zb * sBb + (long)zh * sBh;
    float* Cb       = C + (long)zb * sCb + (long)zh * sCh;

    const int tid = threadIdx.x;
    const int tx = tid % (BN / TN);
    const int ty = tid / (BN / TN);
    const int row0 = blockIdx.y * BM;
    const int col0 = blockIdx.x * BN;

    float acc[TM][TN] = {};

    for (int k0 = 0; k0 < K; k0 += BK) {
        // A tile: BM x BK, float4 along k, store k-major in smem
#pragma unroll
        for (int i = tid; i < BM * KV; i += THREADS) {
            const int m  = i / KV;
            const int kq = (i % KV) * 4;
            const float4 t = *reinterpret_cast<const float4*>(Ab + (long)(row0 + m) * lda + k0 + kq);
            As[kq + 0][m] = t.x; As[kq + 1][m] = t.y; As[kq + 2][m] = t.z; As[kq + 3][m] = t.w;
        }
        // B tile
        if (TRANSB) {
#pragma unroll
            for (int i = tid; i < BN * KV; i += THREADS) {
                const int n  = i / KV;
                const int kq = (i % KV) * 4;
                const float4 t = *reinterpret_cast<const float4*>(Bb + (long)(col0 + n) * ldb + k0 + kq);
                Bs[kq + 0][n] = t.x; Bs[kq + 1][n] = t.y; Bs[kq + 2][n] = t.z; Bs[kq + 3][n] = t.w;
            }
        } else {
#pragma unroll
            for (int i = tid; i < BK * BN; i += THREADS) {
                const int kk = i / BN;
                const int n  = i % BN;
                Bs[kk][n] = Bb[(long)(k0 + kk) * ldb + col0 + n];
            }
        }
        __syncthreads();
#pragma unroll
        for (int kk = 0; kk < BK; kk++) {
            float a[TM], b[TN];
#pragma unroll
            for (int i = 0; i < TM; i += 4) {
                const float4 t = *reinterpret_cast<const float4*>(&As[kk][ty * TM + i]);
                a[i] = t.x; a[i + 1] = t.y; a[i + 2] = t.z; a[i + 3] = t.w;
            }
#pragma unroll
            for (int j = 0; j < TN; j += 4) {
                const float4 t = *reinterpret_cast<const float4*>(&Bs[kk][tx * TN + j]);
                b[j] = t.x; b[j + 1] = t.y; b[j + 2] = t.z; b[j + 3] = t.w;
            }
#pragma unroll
            for (int i = 0; i < TM; i++)
#pragma unroll
                for (int j = 0; j < TN; j++)
                    acc[i][j] = fmaf(a[i], b[j], acc[i][j]);
        }
        __syncthreads();
    }

    // epilogue
#pragma unroll
    for (int i = 0; i < TM; i++) {
        const long r = row0 + ty * TM + i;
#pragma unroll
        for (int j = 0; j < TN; j++) {
            const long c = col0 + tx * TN + j;
            float v = acc[i][j] * alpha;
            if (bias) v += bias[c];
            if (GELU) v = 0.5f * v * (1.0f + erff(v * 0.70710678118654752f));
            if (res)  v += res[r * ldc + c];   // residual only used for batch=1 GEMMs
            Cb[r * ldc + c] = v;
        }
    }
}

// ---------------- launch ----------------
extern "C" void kernel_launch(void* const* d_in, const int* in_sizes, int n_in,
                              void* d_out, int out_size) {
    (void)in_sizes; (void)n_in; (void)out_size;
    const float* x     = (const float*)d_in[0];
    const float* ln1g  = (const float*)d_in[1];
    const float* ln1b  = (const float*)d_in[2];
    const float* ln2g  = (const float*)d_in[3];
    const float* ln2b  = (const float*)d_in[4];
    const float* wqkv  = (const float*)d_in[5];
    const float* bqkv  = (const float*)d_in[6];
    const float* wproj = (const float*)d_in[7];
    const float* bproj = (const float*)d_in[8];
    const float* wfc1  = (const float*)d_in[9];
    const float* bfc1  = (const float*)d_in[10];
    const float* wfc2  = (const float*)d_in[11];
    const float* bfc2  = (const float*)d_in[12];
    float* out = (float*)d_out;

    float *h, *qkv, *sc, *y, *x1, *ff;
    cudaGetSymbolAddress((void**)&h,   g_h);
    cudaGetSymbolAddress((void**)&qkv, g_qkv);
    cudaGetSymbolAddress((void**)&sc,  g_sc);
    cudaGetSymbolAddress((void**)&y,   g_y);
    cudaGetSymbolAddress((void**)&x1,  g_x1);
    cudaGetSymbolAddress((void**)&ff,  g_ff);

    const long TT = (long)SEQ * SEQ;          // 2048*2048
    const long QKVROW = 3L * DMODEL;          // 3072

    // 1) h = LN1(x)
    ln_k<<<NROWS, 256>>>(x, ln1g, ln1b, h);

    // 2) qkv = h @ w_qkv + b_qkv      [4096,1024] x [1024,3072]
    gemm_k<128,128,8,8,8,false,false><<<dim3(3072/128, NROWS/128, 1), 256>>>(
        h, wqkv, bqkv, nullptr, qkv, DMODEL,
        DMODEL, QKVROW, QKVROW, 1, 0,0, 0,0, 0,0, 1.0f);

    // 3) scores[z=b*16+h] = 0.125 * Q_bh @ K_bh^T    M=N=2048, K=64, 32 batches
    gemm_k<128,128,8,8,8,true,false><<<dim3(SEQ/128, SEQ/128, 32), 256>>>(
        qkv, qkv + DMODEL, nullptr, nullptr, sc, HDIM,
        QKVROW, QKVROW, SEQ,
        NHEAD, (long)SEQ * QKVROW, HDIM, (long)SEQ * QKVROW, HDIM,
        (long)NHEAD * TT, TT, 0.125f);

    // 4) softmax over 65536 rows of 2048
    softmax_k<<<2 * NHEAD * SEQ, 256>>>(sc);

    // 5) y_bh = P_bh @ V_bh           M=2048, N=64, K=2048, 32 batches
    gemm_k<64,64,16,4,4,false,false><<<dim3(1, SEQ/64, 32), 256>>>(
        sc, qkv + 2 * DMODEL, nullptr, nullptr, y, SEQ,
        SEQ, QKVROW, DMODEL,
        NHEAD, (long)NHEAD * TT, TT, (long)SEQ * QKVROW, HDIM,
        (long)SEQ * DMODEL, HDIM, 1.0f);

    // 6) x1 = x + y @ w_proj + b_proj
    gemm_k<128,128,8,8,8,false,false><<<dim3(DMODEL/128, NROWS/128, 1), 256>>>(
        y, wproj, bproj, x, x1, DMODEL,
        DMODEL, DMODEL, DMODEL, 1, 0,0, 0,0, 0,0, 1.0f);

    // 7) h = LN2(x1)
    ln_k<<<NROWS, 256>>>(x1, ln2g, ln2b, h);

    // 8) ff = gelu(h @ w_fc1 + b_fc1)   [4096,1024] x [1024,4096]
    gemm_k<128,128,8,8,8,false,true><<<dim3(FFDIM/128, NROWS/128, 1), 256>>>(
        h, wfc1, bfc1, nullptr, ff, DMODEL,
        DMODEL, FFDIM, FFDIM, 1, 0,0, 0,0, 0,0, 1.0f);

    // 9) out = x1 + ff @ w_fc2 + b_fc2  [4096,4096] x [4096,1024]
    gemm_k<128,128,8,8,8,false,false><<<dim3(DMODEL/128, NROWS/128, 1), 256>>>(
        ff, wfc2, bfc2, x1, out, FFDIM,
        FFDIM, DMODEL, DMODEL, 1, 0,0, 0,0, 0,0, 1.0f);
}

// round 3
// speedup vs baseline: 4.1046x; 4.1046x over previous
#include <cuda_runtime.h>
#include <cuda_fp16.h>
#include <math.h>

// Problem constants: B=2, T=2048, D=1024, H=16, HD=64, FF=4096
#define NROWS 4096            // B*T
#define DMODEL 1024
#define NHEAD 16
#define HDIM 64
#define SEQ 2048
#define FFDIM 4096

// ---------------- scratch (static device globals; no allocation) ----------------
__device__ __half g_h16  [(size_t)NROWS * DMODEL];            // LN output (fp16)
__device__ __half g_qkv16[(size_t)NROWS * 3 * DMODEL];        // qkv (fp16)
__device__ __half g_sc16 [(size_t)2 * NHEAD * SEQ * SEQ];     // 256 MB scores/probs (fp16)
__device__ __half g_y16  [(size_t)NROWS * DMODEL];            // attention out (fp16)
__device__ float  g_x1   [(size_t)NROWS * DMODEL];            // residual 1 (fp32)
__device__ __half g_ff16 [(size_t)NROWS * FFDIM];             // gelu(fc1) (fp16)
// fp16 weight copies
__device__ __half g_wqkv16[(size_t)DMODEL * 3 * DMODEL];
__device__ __half g_wproj16[(size_t)DMODEL * DMODEL];
__device__ __half g_wfc1_16[(size_t)DMODEL * FFDIM];
__device__ __half g_wfc2_16[(size_t)FFDIM * DMODEL];

// ---------------- helpers ----------------
__device__ __forceinline__ unsigned smem_u32(const void* p) {
    return (unsigned)__cvta_generic_to_shared(p);
}

#define LDSM_X4(R0,R1,R2,R3,ADDR) \
    asm volatile("ldmatrix.sync.aligned.m8n8.x4.shared.b16 {%0,%1,%2,%3}, [%4];" \
                 : "=r"(R0),"=r"(R1),"=r"(R2),"=r"(R3) : "r"(ADDR))
#define LDSM_X2(R0,R1,ADDR) \
    asm volatile("ldmatrix.sync.aligned.m8n8.x2.shared.b16 {%0,%1}, [%2];" \
                 : "=r"(R0),"=r"(R1) : "r"(ADDR))
#define LDSM_X2_T(R0,R1,ADDR) \
    asm volatile("ldmatrix.sync.aligned.m8n8.x2.trans.shared.b16 {%0,%1}, [%2];" \
                 : "=r"(R0),"=r"(R1) : "r"(ADDR))
#define MMA16816(C0,C1,C2,C3,A0,A1,A2,A3,B0,B1) \
    asm volatile("mma.sync.aligned.m16n8k16.row.col.f32.f16.f16.f32 " \
                 "{%0,%1,%2,%3}, {%4,%5,%6,%7}, {%8,%9}, {%0,%1,%2,%3};" \
                 : "+f"(C0),"+f"(C1),"+f"(C2),"+f"(C3) \
                 : "r"(A0),"r"(A1),"r"(A2),"r"(A3),"r"(B0),"r"(B1))

// ---------------- fp32 -> fp16 weight convert ----------------
__global__ void f2h_k(const float* __restrict__ s, __half* __restrict__ d, long n) {
    long i = ((long)blockIdx.x * 256 + threadIdx.x) * 4;
    if (i < n) {
        float4 t = *reinterpret_cast<const float4*>(s + i);
        __half2* d2 = reinterpret_cast<__half2*>(d + i);
        d2[0] = __floats2half2_rn(t.x, t.y);
        d2[1] = __floats2half2_rn(t.z, t.w);
    }
}

// ---------------- LayerNorm: one block per row of 1024, fp16 out ----------------
__global__ void ln_k(const float* __restrict__ x, const float* __restrict__ g,
                     const float* __restrict__ b, __half* __restrict__ out) {
    __shared__ float red[256];
    const long row = blockIdx.x;
    const float* xr = x + row * (long)DMODEL;
    const int tid = threadIdx.x;
    float v[4];
    float s = 0.f, s2 = 0.f;
#pragma unroll
    for (int i = 0; i < 4; i++) {
        v[i] = xr[tid + i * 256];
        s += v[i];
        s2 += v[i] * v[i];
    }
    red[tid] = s; __syncthreads();
    for (int o = 128; o > 0; o >>= 1) { if (tid < o) red[tid] += red[tid + o]; __syncthreads(); }
    const float mean = red[0] * (1.f / DMODEL);
    __syncthreads();
    red[tid] = s2; __syncthreads();
    for (int o = 128; o > 0; o >>= 1) { if (tid < o) red[tid] += red[tid + o]; __syncthreads(); }
    const float var = red[0] * (1.f / DMODEL) - mean * mean;
    const float inv = rsqrtf(var + 1e-5f);
#pragma unroll
    for (int i = 0; i < 4; i++) {
        const int c = tid + i * 256;
        out[row * (long)DMODEL + c] = __float2half((v[i] - mean) * inv * g[c] + b[c]);
    }
}

// ---------------- Softmax over rows of length 2048, fp16 in-place ----------------
__global__ void softmax_k(__half* __restrict__ s) {
    __shared__ float red[256];
    const long row = blockIdx.x;
    __half2* p = reinterpret_cast<__half2*>(s + row * (long)SEQ);
    const int tid = threadIdx.x;
    float2 v[4];
    float m = -1e30f;
#pragma unroll
    for (int i = 0; i < 4; i++) {
        v[i] = __half22float2(p[tid + i * 256]);
        m = fmaxf(m, fmaxf(v[i].x, v[i].y));
    }
    red[tid] = m; __syncthreads();
    for (int o = 128; o > 0; o >>= 1) { if (tid < o) red[tid] = fmaxf(red[tid], red[tid + o]); __syncthreads(); }
    m = red[0]; __syncthreads();
    float sum = 0.f;
#pragma unroll
    for (int i = 0; i < 4; i++) {
        v[i].x = __expf(v[i].x - m); v[i].y = __expf(v[i].y - m);
        sum += v[i].x + v[i].y;
    }
    red[tid] = sum; __syncthreads();
    for (int o = 128; o > 0; o >>= 1) { if (tid < o) red[tid] += red[tid + o]; __syncthreads(); }
    const float inv = 1.f / red[0];
#pragma unroll
    for (int i = 0; i < 4; i++)
        p[tid + i * 256] = __floats2half2_rn(v[i].x * inv, v[i].y * inv);
}

// ---------------- Tensor-core GEMM (mma.sync m16n8k16 fp16 -> fp32 acc) --------
// C[z] = alpha * A[z] @ B[z] (+ bias) (+ gelu) (+ res), optional fp16 output.
// TRANSB: B element (k,n) read as B[n*ldb + k] (k contiguous).
// 256 threads = 8 warps, layout 4 (M) x 2 (N). Warp tile = (BM/4) x (BN/2).
template<int BM, int BN, int BK, bool TRANSB, bool GELU, bool OUT_HALF, bool RES>
__global__ __launch_bounds__(256)
void hgemm_k(const __half* __restrict__ A, const __half* __restrict__ B,
             const float* __restrict__ bias, const float* __restrict__ res,
             void* __restrict__ Cout, int K, long lda, long ldb, long ldc,
             int batchH, long sAb, long sAh, long sBb, long sBh, long sCb, long sCh,
             float alpha)
{
    constexpr int TM = BM / 64;  // m16 tiles per warp
    constexpr int TN = BN / 16;  // n8 tiles per warp
    constexpr int KV = BK / 8;   // uint4 chunks along k

    __shared__ __align__(16) __half As[BM][BK + 8];
    constexpr int BROWS = TRANSB ? BN : BK;
    constexpr int BCOLS = TRANSB ? BK : BN;
    __shared__ __align__(16) __half Bs[BROWS][BCOLS + 8];

    const int z  = blockIdx.z;
    const int zb = z / batchH, zh = z % batchH;
    const __half* Ab = A + (long)zb * sAb + (long)zh * sAh;
    const __half* Bb = B + (long)zb * sBb + (long)zh * sBh;

    const int tid = threadIdx.x;
    const int lane = tid & 31;
    const int wid = tid >> 5;
    const int warp_m0 = (wid & 3) * (BM / 4);
    const int warp_n0 = (wid >> 2) * (BN / 2);
    const int row0 = blockIdx.y * BM;
    const int col0 = blockIdx.x * BN;

    float acc[TM][TN][4] = {};

    for (int k0 = 0; k0 < K; k0 += BK) {
        // --- load A tile (row-major BM x BK) ---
#pragma unroll
        for (int i = tid; i < BM * KV; i += 256) {
            const int m  = i / KV;
            const int kq = (i % KV) * 8;
            *reinterpret_cast<uint4*>(&As[m][kq]) =
                *reinterpret_cast<const uint4*>(Ab + (long)(row0 + m) * lda + k0 + kq);
        }
        // --- load B tile ---
        if (TRANSB) {
#pragma unroll
            for (int i = tid; i < BN * KV; i += 256) {
                const int n  = i / KV;
                const int kq = (i % KV) * 8;
                *reinterpret_cast<uint4*>(&Bs[n][kq]) =
                    *reinterpret_cast<const uint4*>(Bb + (long)(col0 + n) * ldb + k0 + kq);
            }
        } else {
            constexpr int NV = BN / 8;
#pragma unroll
            for (int i = tid; i < BK * NV; i += 256) {
                const int kk = i / NV;
                const int nq = (i % NV) * 8;
                *reinterpret_cast<uint4*>(&Bs[kk][nq]) =
                    *reinterpret_cast<const uint4*>(Bb + (long)(k0 + kk) * ldb + col0 + nq);
            }
        }
        __syncthreads();

#pragma unroll
        for (int ks = 0; ks < BK; ks += 16) {
            // A fragments via ldmatrix.x4
            unsigned af[TM][4];
#pragma unroll
            for (int tm = 0; tm < TM; tm++) {
                const int r = warp_m0 + tm * 16 + (lane & 7) + ((lane >> 3) & 1) * 8;
                const int c = ks + (lane >> 4) * 8;
                LDSM_X4(af[tm][0], af[tm][1], af[tm][2], af[tm][3], smem_u32(&As[r][c]));
            }
            // B fragments via ldmatrix.x2
            unsigned bf[TN][2];
#pragma unroll
            for (int tn = 0; tn < TN; tn++) {
                const int l = lane & 15;
                if (TRANSB) {
                    const int r = warp_n0 + tn * 8 + (l & 7);
                    const int c = ks + (l >> 3) * 8;
                    LDSM_X2(bf[tn][0], bf[tn][1], smem_u32(&Bs[r][c]));
                } else {
                    const int r = ks + l;
                    const int c = warp_n0 + tn * 8;
                    LDSM_X2_T(bf[tn][0], bf[tn][1], smem_u32(&Bs[r][c]));
                }
            }
#pragma unroll
            for (int tm = 0; tm < TM; tm++)
#pragma unroll
                for (int tn = 0; tn < TN; tn++)
                    MMA16816(acc[tm][tn][0], acc[tm][tn][1], acc[tm][tn][2], acc[tm][tn][3],
                             af[tm][0], af[tm][1], af[tm][2], af[tm][3],
                             bf[tn][0], bf[tn][1]);
        }
        __syncthreads();
    }

    // --- epilogue ---
    __half* Ch = reinterpret_cast<__half*>(Cout) + (long)zb * sCb + (long)zh * sCh;
    float*  Cf = reinterpret_cast<float*>(Cout)  + (long)zb * sCb + (long)zh * sCh;
#pragma unroll
    for (int tm = 0; tm < TM; tm++) {
#pragma unroll
        for (int tn = 0; tn < TN; tn++) {
            const int r = row0 + warp_m0 + tm * 16 + (lane >> 2);
            const int c = col0 + warp_n0 + tn * 8 + (lane & 3) * 2;
            float v[4] = {acc[tm][tn][0], acc[tm][tn][1], acc[tm][tn][2], acc[tm][tn][3]};
#pragma unroll
            for (int q = 0; q < 4; q++) v[q] *= alpha;
            if (bias) {
                const float b0 = bias[c], b1 = bias[c + 1];
                v[0] += b0; v[1] += b1; v[2] += b0; v[3] += b1;
            }
            if (GELU) {
#pragma unroll
                for (int q = 0; q < 4; q++)
                    v[q] = 0.5f * v[q] * (1.0f + erff(v[q] * 0.70710678118654752f));
            }
            if (RES) {
                v[0] += res[(long)r * ldc + c];
                v[1] += res[(long)r * ldc + c + 1];
                v[2] += res[(long)(r + 8) * ldc + c];
                v[3] += res[(long)(r + 8) * ldc + c + 1];
            }
            if (OUT_HALF) {
                *reinterpret_cast<__half2*>(Ch + (long)r * ldc + c)       = __floats2half2_rn(v[0], v[1]);
                *reinterpret_cast<__half2*>(Ch + (long)(r + 8) * ldc + c) = __floats2half2_rn(v[2], v[3]);
            } else {
                Cf[(long)r * ldc + c]           = v[0];
                Cf[(long)r * ldc + c + 1]       = v[1];
                Cf[(long)(r + 8) * ldc + c]     = v[2];
                Cf[(long)(r + 8) * ldc + c + 1] = v[3];
            }
        }
    }
}

// ---------------- launch ----------------
extern "C" void kernel_launch(void* const* d_in, const int* in_sizes, int n_in,
                              void* d_out, int out_size) {
    (void)in_sizes; (void)n_in; (void)out_size;
    const float* x     = (const float*)d_in[0];
    const float* ln1g  = (const float*)d_in[1];
    const float* ln1b  = (const float*)d_in[2];
    const float* ln2g  = (const float*)d_in[3];
    const float* ln2b  = (const float*)d_in[4];
    const float* wqkv  = (const float*)d_in[5];
    const float* bqkv  = (const float*)d_in[6];
    const float* wproj = (const float*)d_in[7];
    const float* bproj = (const float*)d_in[8];
    const float* wfc1  = (const float*)d_in[9];
    const float* bfc1  = (const float*)d_in[10];
    const float* wfc2  = (const float*)d_in[11];
    const float* bfc2  = (const float*)d_in[12];
    float* out = (float*)d_out;

    __half *h16, *qkv16, *sc16, *y16, *ff16, *wqkv16, *wproj16, *wfc1_16, *wfc2_16;
    float *x1;
    cudaGetSymbolAddress((void**)&h16,     g_h16);
    cudaGetSymbolAddress((void**)&qkv16,   g_qkv16);
    cudaGetSymbolAddress((void**)&sc16,    g_sc16);
    cudaGetSymbolAddress((void**)&y16,     g_y16);
    cudaGetSymbolAddress((void**)&x1,      g_x1);
    cudaGetSymbolAddress((void**)&ff16,    g_ff16);
    cudaGetSymbolAddress((void**)&wqkv16,  g_wqkv16);
    cudaGetSymbolAddress((void**)&wproj16, g_wproj16);
    cudaGetSymbolAddress((void**)&wfc1_16, g_wfc1_16);
    cudaGetSymbolAddress((void**)&wfc2_16, g_wfc2_16);

    const long TT = (long)SEQ * SEQ;
    const long QKVROW = 3L * DMODEL;

    // 0) weight conversions (fp32 -> fp16)
    {
        long n;
        n = (long)DMODEL * 3 * DMODEL; f2h_k<<<(unsigned)((n/4 + 255)/256), 256>>>(wqkv, wqkv16, n);
        n = (long)DMODEL * DMODEL;     f2h_k<<<(unsigned)((n/4 + 255)/256), 256>>>(wproj, wproj16, n);
        n = (long)DMODEL * FFDIM;      f2h_k<<<(unsigned)((n/4 + 255)/256), 256>>>(wfc1, wfc1_16, n);
        n = (long)FFDIM * DMODEL;      f2h_k<<<(unsigned)((n/4 + 255)/256), 256>>>(wfc2, wfc2_16, n);
    }

    // 1) h = LN1(x)  (fp16 out)
    ln_k<<<NROWS, 256>>>(x, ln1g, ln1b, h16);

    // 2) qkv = h @ w_qkv + b_qkv  -> fp16   [4096,1024]x[1024,3072]
    hgemm_k<128,128,32,false,false,true,false><<<dim3(3072/128, NROWS/128, 1), 256>>>(
        h16, wqkv16, bqkv, nullptr, qkv16, DMODEL,
        DMODEL, QKVROW, QKVROW, 1, 0,0, 0,0, 0,0, 1.0f);

    // 3) scores = 0.125 * Q @ K^T  -> fp16   M=N=2048, K=64, 32 batches
    hgemm_k<128,128,32,true,false,true,false><<<dim3(SEQ/128, SEQ/128, 32), 256>>>(
        qkv16, qkv16 + DMODEL, nullptr, nullptr, sc16, HDIM,
        QKVROW, QKVROW, SEQ,
        NHEAD, (long)SEQ * QKVROW, HDIM, (long)SEQ * QKVROW, HDIM,
        (long)NHEAD * TT, TT, 0.125f);

    // 4) softmax (fp16 in-place, fp32 math)
    softmax_k<<<2 * NHEAD * SEQ, 256>>>(sc16);

    // 5) y = P @ V  -> fp16   M=2048, N=64, K=2048, 32 batches
    hgemm_k<128,64,32,false,false,true,false><<<dim3(1, SEQ/128, 32), 256>>>(
        sc16, qkv16 + 2 * DMODEL, nullptr, nullptr, y16, SEQ,
        SEQ, QKVROW, DMODEL,
        NHEAD, (long)NHEAD * TT, TT, (long)SEQ * QKVROW, HDIM,
        (long)SEQ * DMODEL, HDIM, 1.0f);

    // 6) x1 = x + y @ w_proj + b_proj  (fp32 out)
    hgemm_k<128,128,32,false,false,false,true><<<dim3(DMODEL/128, NROWS/128, 1), 256>>>(
        y16, wproj16, bproj, x, x1, DMODEL,
        DMODEL, DMODEL, DMODEL, 1, 0,0, 0,0, 0,0, 1.0f);

    // 7) h = LN2(x1)  (fp16 out)
    ln_k<<<NROWS, 256>>>(x1, ln2g, ln2b, h16);

    // 8) ff = gelu(h @ w_fc1 + b_fc1)  -> fp16   [4096,1024]x[1024,4096]
    hgemm_k<128,128,32,false,true,true,false><<<dim3(FFDIM/128, NROWS/128, 1), 256>>>(
        h16, wfc1_16, bfc1, nullptr, ff16, DMODEL,
        DMODEL, FFDIM, FFDIM, 1, 0,0, 0,0, 0,0, 1.0f);

    // 9) out = x1 + ff @ w_fc2 + b_fc2  (fp32 out)   [4096,4096]x[4096,1024]
    hgemm_k<128,128,32,false,false,false,true><<<dim3(DMODEL/128, NROWS/128, 1), 256>>>(
        ff16, wfc2_16, bfc2, x1, out, FFDIM,
        FFDIM, DMODEL, DMODEL, 1, 0,0, 0,0, 0,0, 1.0f);
}

// round 5
// speedup vs baseline: 5.9303x; 1.4448x over previous
#include <cuda_runtime.h>
#include <cuda_fp16.h>
#include <math.h>

// Problem constants: B=2, T=2048, D=1024, H=16, HD=64, FF=4096
#define NROWS 4096            // B*T
#define DMODEL 1024
#define NHEAD 16
#define HDIM 64
#define SEQ 2048
#define FFDIM 4096

// ---------------- scratch (static device globals; no allocation) ----------------
__device__ __half g_h16  [(size_t)NROWS * DMODEL];            // LN output (fp16)
__device__ __half g_qkv16[(size_t)NROWS * 3 * DMODEL];        // qkv (fp16)
__device__ __half g_y16  [(size_t)NROWS * DMODEL];            // attention out (fp16)
__device__ float  g_x1   [(size_t)NROWS * DMODEL];            // residual 1 (fp32)
__device__ __half g_ff16 [(size_t)NROWS * FFDIM];             // gelu(fc1) (fp16)
// fp16 weight copies
__device__ __half g_wqkv16[(size_t)DMODEL * 3 * DMODEL];
__device__ __half g_wproj16[(size_t)DMODEL * DMODEL];
__device__ __half g_wfc1_16[(size_t)DMODEL * FFDIM];
__device__ __half g_wfc2_16[(size_t)FFDIM * DMODEL];

// ---------------- helpers ----------------
__device__ __forceinline__ unsigned smem_u32(const void* p) {
    return (unsigned)__cvta_generic_to_shared(p);
}
__device__ __forceinline__ unsigned h2u(__half2 h) {
    return *reinterpret_cast<unsigned*>(&h);
}

#define LDSM_X4(R0,R1,R2,R3,ADDR) \
    asm volatile("ldmatrix.sync.aligned.m8n8.x4.shared.b16 {%0,%1,%2,%3}, [%4];" \
                 : "=r"(R0),"=r"(R1),"=r"(R2),"=r"(R3) : "r"(ADDR))
#define LDSM_X2(R0,R1,ADDR) \
    asm volatile("ldmatrix.sync.aligned.m8n8.x2.shared.b16 {%0,%1}, [%2];" \
                 : "=r"(R0),"=r"(R1) : "r"(ADDR))
#define LDSM_X2_T(R0,R1,ADDR) \
    asm volatile("ldmatrix.sync.aligned.m8n8.x2.trans.shared.b16 {%0,%1}, [%2];" \
                 : "=r"(R0),"=r"(R1) : "r"(ADDR))
#define MMA16816(C0,C1,C2,C3,A0,A1,A2,A3,B0,B1) \
    asm volatile("mma.sync.aligned.m16n8k16.row.col.f32.f16.f16.f32 " \
                 "{%0,%1,%2,%3}, {%4,%5,%6,%7}, {%8,%9}, {%0,%1,%2,%3};" \
                 : "+f"(C0),"+f"(C1),"+f"(C2),"+f"(C3) \
                 : "r"(A0),"r"(A1),"r"(A2),"r"(A3),"r"(B0),"r"(B1))
#define CP_ASYNC16(SMEM, GMEM) \
    asm volatile("cp.async.cg.shared.global [%0], [%1], 16;" :: "r"(SMEM), "l"(GMEM))
#define CP_COMMIT() asm volatile("cp.async.commit_group;")
#define CP_WAIT(N)  asm volatile("cp.async.wait_group %0;" :: "n"(N))

// ---------------- fp32 -> fp16 weight convert ----------------
__global__ void f2h_k(const float* __restrict__ s, __half* __restrict__ d, long n) {
    long i = ((long)blockIdx.x * 256 + threadIdx.x) * 4;
    if (i < n) {
        float4 t = *reinterpret_cast<const float4*>(s + i);
        __half2* d2 = reinterpret_cast<__half2*>(d + i);
        d2[0] = __floats2half2_rn(t.x, t.y);
        d2[1] = __floats2half2_rn(t.z, t.w);
    }
}

// ---------------- LayerNorm: one block per row of 1024, fp16 out ----------------
__global__ void ln_k(const float* __restrict__ x, const float* __restrict__ g,
                     const float* __restrict__ b, __half* __restrict__ out) {
    __shared__ float red[256];
    const long row = blockIdx.x;
    const float* xr = x + row * (long)DMODEL;
    const int tid = threadIdx.x;
    float v[4];
    float s = 0.f, s2 = 0.f;
#pragma unroll
    for (int i = 0; i < 4; i++) {
        v[i] = xr[tid + i * 256];
        s += v[i];
        s2 += v[i] * v[i];
    }
    red[tid] = s; __syncthreads();
    for (int o = 128; o > 0; o >>= 1) { if (tid < o) red[tid] += red[tid + o]; __syncthreads(); }
    const float mean = red[0] * (1.f / DMODEL);
    __syncthreads();
    red[tid] = s2; __syncthreads();
    for (int o = 128; o > 0; o >>= 1) { if (tid < o) red[tid] += red[tid + o]; __syncthreads(); }
    const float var = red[0] * (1.f / DMODEL) - mean * mean;
    const float inv = rsqrtf(var + 1e-5f);
#pragma unroll
    for (int i = 0; i < 4; i++) {
        const int c = tid + i * 256;
        out[row * (long)DMODEL + c] = __float2half((v[i] - mean) * inv * g[c] + b[c]);
    }
}

// ---------------- Flash attention: fused QK^T -> softmax -> PV ----------------
// Grid: (SEQ/128, B*NHEAD). Block: 256 threads = 8 warps, each warp owns 16 q-rows.
// Q fragments in registers; K/V tiles of 128 streamed through smem.
__global__ __launch_bounds__(256) void flash_k(const __half* __restrict__ qkv,
                                               __half* __restrict__ y) {
    __shared__ __align__(16) __half Ks[128][72];
    __shared__ __align__(16) __half Vs[128][72];

    const int bh = blockIdx.y;
    const int b = bh >> 4, h = bh & 15;
    const int q0 = blockIdx.x * 128;
    const long base = (long)b * SEQ * (3L * DMODEL);
    const __half* Qg = qkv + base + (long)q0 * (3 * DMODEL) + h * HDIM;
    const __half* Kg = qkv + base + DMODEL + h * HDIM;
    const __half* Vg = qkv + base + 2 * DMODEL + h * HDIM;

    const int tid = threadIdx.x, lane = tid & 31, w = tid >> 5;

    // --- load Q tile into Ks (temp), extract A fragments, then reuse Ks for K ---
    for (int i = tid; i < 128 * 8; i += 256) {
        const int r = i >> 3, cq = (i & 7) * 8;
        *reinterpret_cast<uint4*>(&Ks[r][cq]) =
            *reinterpret_cast<const uint4*>(Qg + (long)r * (3 * DMODEL) + cq);
    }
    __syncthreads();
    unsigned aq[4][4];
    {
        const int r = w * 16 + (lane & 7) + ((lane >> 3) & 1) * 8;
#pragma unroll
        for (int c = 0; c < 4; c++)
            LDSM_X4(aq[c][0], aq[c][1], aq[c][2], aq[c][3],
                    smem_u32(&Ks[r][c * 16 + (lane >> 4) * 8]));
    }
    __syncthreads();

    float m0 = -1e30f, m1 = -1e30f, l0 = 0.f, l1 = 0.f;
    float o[8][4] = {};

    for (int kv0 = 0; kv0 < SEQ; kv0 += 128) {
        // load K,V tiles
        for (int i = tid; i < 128 * 8; i += 256) {
            const int r = i >> 3, cq = (i & 7) * 8;
            *reinterpret_cast<uint4*>(&Ks[r][cq]) =
                *reinterpret_cast<const uint4*>(Kg + (long)(kv0 + r) * (3 * DMODEL) + cq);
            *reinterpret_cast<uint4*>(&Vs[r][cq]) =
                *reinterpret_cast<const uint4*>(Vg + (long)(kv0 + r) * (3 * DMODEL) + cq);
        }
        __syncthreads();

        // S = Q K^T : per warp m16 x n128
        float s[16][4] = {};
        const int l = lane & 15;
#pragma unroll
        for (int c = 0; c < 4; c++) {
#pragma unroll
            for (int j = 0; j < 16; j++) {
                unsigned b0, b1;
                LDSM_X2(b0, b1, smem_u32(&Ks[j * 8 + (l & 7)][c * 16 + (l >> 3) * 8]));
                MMA16816(s[j][0], s[j][1], s[j][2], s[j][3],
                         aq[c][0], aq[c][1], aq[c][2], aq[c][3], b0, b1);
            }
        }
        // online softmax (fp32). rows: r0 = lane>>2, r1 = r0+8
        float mx0 = -1e30f, mx1 = -1e30f;
#pragma unroll
        for (int j = 0; j < 16; j++) {
#pragma unroll
            for (int q = 0; q < 4; q++) s[j][q] *= 0.125f;
            mx0 = fmaxf(mx0, fmaxf(s[j][0], s[j][1]));
            mx1 = fmaxf(mx1, fmaxf(s[j][2], s[j][3]));
        }
        mx0 = fmaxf(mx0, __shfl_xor_sync(~0u, mx0, 1));
        mx0 = fmaxf(mx0, __shfl_xor_sync(~0u, mx0, 2));
        mx1 = fmaxf(mx1, __shfl_xor_sync(~0u, mx1, 1));
        mx1 = fmaxf(mx1, __shfl_xor_sync(~0u, mx1, 2));
        const float nm0 = fmaxf(m0, mx0), nm1 = fmaxf(m1, mx1);
        const float sc0 = __expf(m0 - nm0), sc1 = __expf(m1 - nm1);
        m0 = nm0; m1 = nm1;
        float sum0 = 0.f, sum1 = 0.f;
#pragma unroll
        for (int j = 0; j < 16; j++) {
            s[j][0] = __expf(s[j][0] - m0); s[j][1] = __expf(s[j][1] - m0);
            s[j][2] = __expf(s[j][2] - m1); s[j][3] = __expf(s[j][3] - m1);
            sum0 += s[j][0] + s[j][1];
            sum1 += s[j][2] + s[j][3];
        }
        sum0 += __shfl_xor_sync(~0u, sum0, 1); sum0 += __shfl_xor_sync(~0u, sum0, 2);
        sum1 += __shfl_xor_sync(~0u, sum1, 1); sum1 += __shfl_xor_sync(~0u, sum1, 2);
        l0 = l0 * sc0 + sum0; l1 = l1 * sc1 + sum1;
#pragma unroll
        for (int t = 0; t < 8; t++) {
            o[t][0] *= sc0; o[t][1] *= sc0; o[t][2] *= sc1; o[t][3] *= sc1;
        }
        // O += P V  (P: C-frag layout == A-frag layout identity)
#pragma unroll
        for (int c = 0; c < 8; c++) {
            const unsigned a0 = h2u(__floats2half2_rn(s[2*c][0],   s[2*c][1]));
            const unsigned a1 = h2u(__floats2half2_rn(s[2*c][2],   s[2*c][3]));
            const unsigned a2 = h2u(__floats2half2_rn(s[2*c+1][0], s[2*c+1][1]));
            const unsigned a3 = h2u(__floats2half2_rn(s[2*c+1][2], s[2*c+1][3]));
#pragma unroll
            for (int t = 0; t < 8; t++) {
                unsigned b0, b1;
                LDSM_X2_T(b0, b1, smem_u32(&Vs[c * 16 + l][t * 8]));
                MMA16816(o[t][0], o[t][1], o[t][2], o[t][3], a0, a1, a2, a3, b0, b1);
            }
        }
        __syncthreads();
    }

    // epilogue: O / l -> y16 [token][h*64+col]
    const float i0 = 1.f / l0, i1 = 1.f / l1;
    __half* Yg = y + (long)(b * SEQ + q0) * DMODEL + h * HDIM;
    const int r = lane >> 2, cq = (lane & 3) * 2;
#pragma unroll
    for (int t = 0; t < 8; t++) {
        *reinterpret_cast<__half2*>(Yg + (long)(w * 16 + r) * DMODEL + t * 8 + cq) =
            __floats2half2_rn(o[t][0] * i0, o[t][1] * i0);
        *reinterpret_cast<__half2*>(Yg + (long)(w * 16 + r + 8) * DMODEL + t * 8 + cq) =
            __floats2half2_rn(o[t][2] * i1, o[t][3] * i1);
    }
}

// ---------------- Dense GEMM, cp.async 2-stage pipeline ----------------
// C = A[M,K] @ B[K,N] (+bias)(+gelu)(+res). 8 warps: 4(M) x 2(N).
template<int BM, int BN, int BK, bool GELU, bool OUT_HALF, bool RES>
__global__ __launch_bounds__(256)
void hgemm2_k(const __half* __restrict__ A, const __half* __restrict__ B,
              const float* __restrict__ bias, const float* __restrict__ res,
              void* __restrict__ Cout, int K, long lda, long ldb, long ldc,
              float alpha)
{
    constexpr int TM = BM / 64;
    constexpr int TN = BN / 16;
    constexpr int KV = BK / 8;
    constexpr int NV = BN / 8;

    __shared__ __align__(16) __half As[2][BM][BK + 8];
    __shared__ __align__(16) __half Bs[2][BK][BN + 8];

    const int tid = threadIdx.x;
    const int lane = tid & 31;
    const int wid = tid >> 5;
    const int warp_m0 = (wid & 3) * (BM / 4);
    const int warp_n0 = (wid >> 2) * (BN / 2);
    const int row0 = blockIdx.y * BM;
    const int col0 = blockIdx.x * BN;

    float acc[TM][TN][4] = {};

    auto load_stage = [&](int st, int k0) {
#pragma unroll
        for (int i = tid; i < BM * KV; i += 256) {
            const int m  = i / KV;
            const int kq = (i % KV) * 8;
            CP_ASYNC16(smem_u32(&As[st][m][kq]), A + (long)(row0 + m) * lda + k0 + kq);
        }
#pragma unroll
        for (int i = tid; i < BK * NV; i += 256) {
            const int kk = i / NV;
            const int nq = (i % NV) * 8;
            CP_ASYNC16(smem_u32(&Bs[st][kk][nq]), B + (long)(k0 + kk) * ldb + col0 + nq);
        }
        CP_COMMIT();
    };

    load_stage(0, 0);
    const int KT = K / BK;

    for (int kt = 0; kt < KT; kt++) {
        if (kt + 1 < KT) {
            load_stage((kt + 1) & 1, (kt + 1) * BK);
            CP_WAIT(1);
        } else {
            CP_WAIT(0);
        }
        __syncthreads();
        const int st = kt & 1;

#pragma unroll
        for (int ks = 0; ks < BK; ks += 16) {
            unsigned af[TM][4];
#pragma unroll
            for (int tm = 0; tm < TM; tm++) {
                const int r = warp_m0 + tm * 16 + (lane & 7) + ((lane >> 3) & 1) * 8;
                const int c = ks + (lane >> 4) * 8;
                LDSM_X4(af[tm][0], af[tm][1], af[tm][2], af[tm][3],
                        smem_u32(&As[st][r][c]));
            }
            unsigned bf[TN][2];
#pragma unroll
            for (int tn = 0; tn < TN; tn++) {
                const int r = ks + (lane & 15);
                const int c = warp_n0 + tn * 8;
                LDSM_X2_T(bf[tn][0], bf[tn][1], smem_u32(&Bs[st][r][c]));
            }
#pragma unroll
            for (int tm = 0; tm < TM; tm++)
#pragma unroll
                for (int tn = 0; tn < TN; tn++)
                    MMA16816(acc[tm][tn][0], acc[tm][tn][1], acc[tm][tn][2], acc[tm][tn][3],
                             af[tm][0], af[tm][1], af[tm][2], af[tm][3],
                             bf[tn][0], bf[tn][1]);
        }
        __syncthreads();
    }

    // epilogue
    __half* Ch = reinterpret_cast<__half*>(Cout);
    float*  Cf = reinterpret_cast<float*>(Cout);
#pragma unroll
    for (int tm = 0; tm < TM; tm++) {
#pragma unroll
        for (int tn = 0; tn < TN; tn++) {
            const int r = row0 + warp_m0 + tm * 16 + (lane >> 2);
            const int c = col0 + warp_n0 + tn * 8 + (lane & 3) * 2;
            float v[4] = {acc[tm][tn][0], acc[tm][tn][1], acc[tm][tn][2], acc[tm][tn][3]};
#pragma unroll
            for (int q = 0; q < 4; q++) v[q] *= alpha;
            if (bias) {
                const float b0 = bias[c], b1 = bias[c + 1];
                v[0] += b0; v[1] += b1; v[2] += b0; v[3] += b1;
            }
            if (GELU) {
#pragma unroll
                for (int q = 0; q < 4; q++)
                    v[q] = 0.5f * v[q] * (1.0f + erff(v[q] * 0.70710678118654752f));
            }
            if (RES) {
                v[0] += res[(long)r * ldc + c];
                v[1] += res[(long)r * ldc + c + 1];
                v[2] += res[(long)(r + 8) * ldc + c];
                v[3] += res[(long)(r + 8) * ldc + c + 1];
            }
            if (OUT_HALF) {
                *reinterpret_cast<__half2*>(Ch + (long)r * ldc + c)       = __floats2half2_rn(v[0], v[1]);
                *reinterpret_cast<__half2*>(Ch + (long)(r + 8) * ldc + c) = __floats2half2_rn(v[2], v[3]);
            } else {
                Cf[(long)r * ldc + c]           = v[0];
                Cf[(long)r * ldc + c + 1]       = v[1];
                Cf[(long)(r + 8) * ldc + c]     = v[2];
                Cf[(long)(r + 8) * ldc + c + 1] = v[3];
            }
        }
    }
}

// ---------------- launch ----------------
extern "C" void kernel_launch(void* const* d_in, const int* in_sizes, int n_in,
                              void* d_out, int out_size) {
    (void)in_sizes; (void)n_in; (void)out_size;
    const float* x     = (const float*)d_in[0];
    const float* ln1g  = (const float*)d_in[1];
    const float* ln1b  = (const float*)d_in[2];
    const float* ln2g  = (const float*)d_in[3];
    const float* ln2b  = (const float*)d_in[4];
    const float* wqkv  = (const float*)d_in[5];
    const float* bqkv  = (const float*)d_in[6];
    const float* wproj = (const float*)d_in[7];
    const float* bproj = (const float*)d_in[8];
    const float* wfc1  = (const float*)d_in[9];
    const float* bfc1  = (const float*)d_in[10];
    const float* wfc2  = (const float*)d_in[11];
    const float* bfc2  = (const float*)d_in[12];
    float* out = (float*)d_out;

    __half *h16, *qkv16, *y16, *ff16, *wqkv16, *wproj16, *wfc1_16, *wfc2_16;
    float *x1;
    cudaGetSymbolAddress((void**)&h16,     g_h16);
    cudaGetSymbolAddress((void**)&qkv16,   g_qkv16);
    cudaGetSymbolAddress((void**)&y16,     g_y16);
    cudaGetSymbolAddress((void**)&x1,      g_x1);
    cudaGetSymbolAddress((void**)&ff16,    g_ff16);
    cudaGetSymbolAddress((void**)&wqkv16,  g_wqkv16);
    cudaGetSymbolAddress((void**)&wproj16, g_wproj16);
    cudaGetSymbolAddress((void**)&wfc1_16, g_wfc1_16);
    cudaGetSymbolAddress((void**)&wfc2_16, g_wfc2_16);

    const long QKVROW = 3L * DMODEL;

    // 0) weight conversions
    {
        long n;
        n = (long)DMODEL * 3 * DMODEL; f2h_k<<<(unsigned)((n/4 + 255)/256), 256>>>(wqkv, wqkv16, n);
        n = (long)DMODEL * DMODEL;     f2h_k<<<(unsigned)((n/4 + 255)/256), 256>>>(wproj, wproj16, n);
        n = (long)DMODEL * FFDIM;      f2h_k<<<(unsigned)((n/4 + 255)/256), 256>>>(wfc1, wfc1_16, n);
        n = (long)FFDIM * DMODEL;      f2h_k<<<(unsigned)((n/4 + 255)/256), 256>>>(wfc2, wfc2_16, n);
    }

    // 1) h = LN1(x)
    ln_k<<<NROWS, 256>>>(x, ln1g, ln1b, h16);

    // 2) qkv = h @ w_qkv + b_qkv -> fp16
    hgemm2_k<128,128,32,false,true,false><<<dim3(3072/128, NROWS/128), 256>>>(
        h16, wqkv16, bqkv, nullptr, qkv16, DMODEL, DMODEL, QKVROW, QKVROW, 1.0f);

    // 3) fused attention -> y16
    flash_k<<<dim3(SEQ/128, 2 * NHEAD), 256>>>(qkv16, y16);

    // 4) x1 = x + y @ w_proj + b_proj (fp32)
    hgemm2_k<128,128,32,false,false,true><<<dim3(DMODEL/128, NROWS/128), 256>>>(
        y16, wproj16, bproj, x, x1, DMODEL, DMODEL, DMODEL, DMODEL, 1.0f);

    // 5) h = LN2(x1)
    ln_k<<<NROWS, 256>>>(x1, ln2g, ln2b, h16);

    // 6) ff = gelu(h @ w_fc1 + b_fc1) -> fp16
    hgemm2_k<128,128,32,true,true,false><<<dim3(FFDIM/128, NROWS/128), 256>>>(
        h16, wfc1_16, bfc1, nullptr, ff16, DMODEL, DMODEL, FFDIM, FFDIM, 1.0f);

    // 7) out = x1 + ff @ w_fc2 + b_fc2 (fp32)
    hgemm2_k<128,128,32,false,false,true><<<dim3(DMODEL/128, NROWS/128), 256>>>(
        ff16, wfc2_16, bfc2, x1, out, FFDIM, FFDIM, DMODEL, DMODEL, 1.0f);
}

// round 8
// speedup vs baseline: 6.3599x; 1.0724x over previous
#include <cuda_runtime.h>
#include <cuda_fp16.h>
#include <cstdint>
#include <math.h>

// Problem constants: B=2, T=2048, D=1024, H=16, HD=64, FF=4096
#define NROWS 4096
#define DMODEL 1024
#define NHEAD 16
#define HDIM 64
#define SEQ 2048
#define FFDIM 4096

// ---------------- scratch ----------------
__device__ __half g_h16  [(size_t)NROWS * DMODEL];
__device__ __half g_qkv16[(size_t)NROWS * 3 * DMODEL];
__device__ __half g_y16  [(size_t)NROWS * DMODEL];
__device__ float  g_x1   [(size_t)NROWS * DMODEL];
__device__ __half g_ff16 [(size_t)NROWS * FFDIM];
__device__ __half g_wqkv16[(size_t)DMODEL * 3 * DMODEL];
__device__ __half g_wproj16[(size_t)DMODEL * DMODEL];
__device__ __half g_wfc1_16[(size_t)DMODEL * FFDIM];
__device__ __half g_wfc2_16[(size_t)FFDIM * DMODEL];

// ---------------- helpers ----------------
__device__ __forceinline__ unsigned smem_u32(const void* p) {
    return (unsigned)__cvta_generic_to_shared(p);
}
__device__ __forceinline__ unsigned h2u(__half2 h) {
    return *reinterpret_cast<unsigned*>(&h);
}

#define LDSM_X4(R0,R1,R2,R3,ADDR) \
    asm volatile("ldmatrix.sync.aligned.m8n8.x4.shared.b16 {%0,%1,%2,%3}, [%4];" \
                 : "=r"(R0),"=r"(R1),"=r"(R2),"=r"(R3) : "r"(ADDR))
#define LDSM_X2(R0,R1,ADDR) \
    asm volatile("ldmatrix.sync.aligned.m8n8.x2.shared.b16 {%0,%1}, [%2];" \
                 : "=r"(R0),"=r"(R1) : "r"(ADDR))
#define LDSM_X2_T(R0,R1,ADDR) \
    asm volatile("ldmatrix.sync.aligned.m8n8.x2.trans.shared.b16 {%0,%1}, [%2];" \
                 : "=r"(R0),"=r"(R1) : "r"(ADDR))
#define MMA16816(C0,C1,C2,C3,A0,A1,A2,A3,B0,B1) \
    asm volatile("mma.sync.aligned.m16n8k16.row.col.f32.f16.f16.f32 " \
                 "{%0,%1,%2,%3}, {%4,%5,%6,%7}, {%8,%9}, {%0,%1,%2,%3};" \
                 : "+f"(C0),"+f"(C1),"+f"(C2),"+f"(C3) \
                 : "r"(A0),"r"(A1),"r"(A2),"r"(A3),"r"(B0),"r"(B1))
#define CP_ASYNC16(SMEM, GMEM) \
    asm volatile("cp.async.cg.shared.global [%0], [%1], 16;" :: "r"(SMEM), "l"(GMEM))
#define CP_COMMIT() asm volatile("cp.async.commit_group;")
#define CP_WAIT(N)  asm volatile("cp.async.wait_group %0;" :: "n"(N))

// ---------------- fp32 -> fp16 weight convert ----------------
__global__ void f2h_k(const float* __restrict__ s, __half* __restrict__ d, long n) {
    long i = ((long)blockIdx.x * 256 + threadIdx.x) * 4;
    if (i < n) {
        float4 t = *reinterpret_cast<const float4*>(s + i);
        __half2* d2 = reinterpret_cast<__half2*>(d + i);
        d2[0] = __floats2half2_rn(t.x, t.y);
        d2[1] = __floats2half2_rn(t.z, t.w);
    }
}

// ---------------- LayerNorm ----------------
__global__ void ln_k(const float* __restrict__ x, const float* __restrict__ g,
                     const float* __restrict__ b, __half* __restrict__ out) {
    __shared__ float red[256];
    const long row = blockIdx.x;
    const float* xr = x + row * (long)DMODEL;
    const int tid = threadIdx.x;
    float v[4];
    float s = 0.f, s2 = 0.f;
#pragma unroll
    for (int i = 0; i < 4; i++) {
        v[i] = xr[tid + i * 256];
        s += v[i]; s2 += v[i] * v[i];
    }
    red[tid] = s; __syncthreads();
    for (int o = 128; o > 0; o >>= 1) { if (tid < o) red[tid] += red[tid + o]; __syncthreads(); }
    const float mean = red[0] * (1.f / DMODEL);
    __syncthreads();
    red[tid] = s2; __syncthreads();
    for (int o = 128; o > 0; o >>= 1) { if (tid < o) red[tid] += red[tid + o]; __syncthreads(); }
    const float var = red[0] * (1.f / DMODEL) - mean * mean;
    const float inv = rsqrtf(var + 1e-5f);
#pragma unroll
    for (int i = 0; i < 4; i++) {
        const int c = tid + i * 256;
        out[row * (long)DMODEL + c] = __float2half((v[i] - mean) * inv * g[c] + b[c]);
    }
}

// ---------------- Flash attention (unchanged, known-good) ----------------
__global__ __launch_bounds__(256) void flash_k(const __half* __restrict__ qkv,
                                               __half* __restrict__ y) {
    __shared__ __align__(16) __half Ks[128][72];
    __shared__ __align__(16) __half Vs[128][72];

    const int bh = blockIdx.y;
    const int b = bh >> 4, h = bh & 15;
    const int q0 = blockIdx.x * 128;
    const long base = (long)b * SEQ * (3L * DMODEL);
    const __half* Qg = qkv + base + (long)q0 * (3 * DMODEL) + h * HDIM;
    const __half* Kg = qkv + base + DMODEL + h * HDIM;
    const __half* Vg = qkv + base + 2 * DMODEL + h * HDIM;

    const int tid = threadIdx.x, lane = tid & 31, w = tid >> 5;

    for (int i = tid; i < 128 * 8; i += 256) {
        const int r = i >> 3, cq = (i & 7) * 8;
        *reinterpret_cast<uint4*>(&Ks[r][cq]) =
            *reinterpret_cast<const uint4*>(Qg + (long)r * (3 * DMODEL) + cq);
    }
    __syncthreads();
    unsigned aq[4][4];
    {
        const int r = w * 16 + (lane & 7) + ((lane >> 3) & 1) * 8;
#pragma unroll
        for (int c = 0; c < 4; c++)
            LDSM_X4(aq[c][0], aq[c][1], aq[c][2], aq[c][3],
                    smem_u32(&Ks[r][c * 16 + (lane >> 4) * 8]));
    }
    __syncthreads();

    float m0 = -1e30f, m1 = -1e30f, l0 = 0.f, l1 = 0.f;
    float o[8][4] = {};

    for (int kv0 = 0; kv0 < SEQ; kv0 += 128) {
        for (int i = tid; i < 128 * 8; i += 256) {
            const int r = i >> 3, cq = (i & 7) * 8;
            *reinterpret_cast<uint4*>(&Ks[r][cq]) =
                *reinterpret_cast<const uint4*>(Kg + (long)(kv0 + r) * (3 * DMODEL) + cq);
            *reinterpret_cast<uint4*>(&Vs[r][cq]) =
                *reinterpret_cast<const uint4*>(Vg + (long)(kv0 + r) * (3 * DMODEL) + cq);
        }
        __syncthreads();

        float s[16][4] = {};
        const int l = lane & 15;
#pragma unroll
        for (int c = 0; c < 4; c++) {
#pragma unroll
            for (int j = 0; j < 16; j++) {
                unsigned b0, b1;
                LDSM_X2(b0, b1, smem_u32(&Ks[j * 8 + (l & 7)][c * 16 + (l >> 3) * 8]));
                MMA16816(s[j][0], s[j][1], s[j][2], s[j][3],
                         aq[c][0], aq[c][1], aq[c][2], aq[c][3], b0, b1);
            }
        }
        float mx0 = -1e30f, mx1 = -1e30f;
#pragma unroll
        for (int j = 0; j < 16; j++) {
#pragma unroll
            for (int q = 0; q < 4; q++) s[j][q] *= 0.125f;
            mx0 = fmaxf(mx0, fmaxf(s[j][0], s[j][1]));
            mx1 = fmaxf(mx1, fmaxf(s[j][2], s[j][3]));
        }
        mx0 = fmaxf(mx0, __shfl_xor_sync(~0u, mx0, 1));
        mx0 = fmaxf(mx0, __shfl_xor_sync(~0u, mx0, 2));
        mx1 = fmaxf(mx1, __shfl_xor_sync(~0u, mx1, 1));
        mx1 = fmaxf(mx1, __shfl_xor_sync(~0u, mx1, 2));
        const float nm0 = fmaxf(m0, mx0), nm1 = fmaxf(m1, mx1);
        const float sc0 = __expf(m0 - nm0), sc1 = __expf(m1 - nm1);
        m0 = nm0; m1 = nm1;
        float sum0 = 0.f, sum1 = 0.f;
#pragma unroll
        for (int j = 0; j < 16; j++) {
            s[j][0] = __expf(s[j][0] - m0); s[j][1] = __expf(s[j][1] - m0);
            s[j][2] = __expf(s[j][2] - m1); s[j][3] = __expf(s[j][3] - m1);
            sum0 += s[j][0] + s[j][1];
            sum1 += s[j][2] + s[j][3];
        }
        sum0 += __shfl_xor_sync(~0u, sum0, 1); sum0 += __shfl_xor_sync(~0u, sum0, 2);
        sum1 += __shfl_xor_sync(~0u, sum1, 1); sum1 += __shfl_xor_sync(~0u, sum1, 2);
        l0 = l0 * sc0 + sum0; l1 = l1 * sc1 + sum1;
#pragma unroll
        for (int t = 0; t < 8; t++) {
            o[t][0] *= sc0; o[t][1] *= sc0; o[t][2] *= sc1; o[t][3] *= sc1;
        }
#pragma unroll
        for (int c = 0; c < 8; c++) {
            const unsigned a0 = h2u(__floats2half2_rn(s[2*c][0],   s[2*c][1]));
            const unsigned a1 = h2u(__floats2half2_rn(s[2*c][2],   s[2*c][3]));
            const unsigned a2 = h2u(__floats2half2_rn(s[2*c+1][0], s[2*c+1][1]));
            const unsigned a3 = h2u(__floats2half2_rn(s[2*c+1][2], s[2*c+1][3]));
#pragma unroll
            for (int t = 0; t < 8; t++) {
                unsigned b0, b1;
                LDSM_X2_T(b0, b1, smem_u32(&Vs[c * 16 + l][t * 8]));
                MMA16816(o[t][0], o[t][1], o[t][2], o[t][3], a0, a1, a2, a3, b0, b1);
            }
        }
        __syncthreads();
    }

    const float i0 = 1.f / l0, i1 = 1.f / l1;
    __half* Yg = y + (long)(b * SEQ + q0) * DMODEL + h * HDIM;
    const int r = lane >> 2, cq = (lane & 3) * 2;
#pragma unroll
    for (int t = 0; t < 8; t++) {
        *reinterpret_cast<__half2*>(Yg + (long)(w * 16 + r) * DMODEL + t * 8 + cq) =
            __floats2half2_rn(o[t][0] * i0, o[t][1] * i0);
        *reinterpret_cast<__half2*>(Yg + (long)(w * 16 + r + 8) * DMODEL + t * 8 + cq) =
            __floats2half2_rn(o[t][2] * i1, o[t][3] * i1);
    }
}

// ---------------- Dense GEMM: 3-stage cp.async, BK=64, 1 barrier/tile ----------
// C = A[M,K] @ B[K,N] (+bias)(+gelu)(+res). BM=128, BN=128. 8 warps: 4(M)x2(N).
// Dynamic smem ring: As[3][128][72], Bs[3][64][136].
template<bool GELU, bool OUT_HALF, bool RES>
__global__ __launch_bounds__(256)
void hgemm3_k(const __half* __restrict__ A, const __half* __restrict__ B,
              const float* __restrict__ bias, const float* __restrict__ res,
              void* __restrict__ Cout, int K, long lda, long ldb, long ldc,
              float alpha)
{
    constexpr int BK = 64;
    constexpr int APITCH = 72;    // halves per A row
    constexpr int BPITCH = 136;   // halves per B row
    constexpr int AS_H = 128 * APITCH;   // halves per A stage
    constexpr int BS_H = BK * BPITCH;    // halves per B stage

    extern __shared__ __align__(16) __half dyn[];
    __half* Asm = dyn;                 // [3][128][72]
    __half* Bsm = dyn + 3 * AS_H;      // [3][64][136]

    const int tid = threadIdx.x;
    const int lane = tid & 31;
    const int wid = tid >> 5;
    const int warp_m0 = (wid & 3) * 32;
    const int warp_n0 = (wid >> 2) * 64;
    const int row0 = blockIdx.y * 128;
    const int col0 = blockIdx.x * 128;

    float acc[2][8][4] = {};

    auto load_stage = [&](int st, int k0) {
        __half* As = Asm + st * AS_H;
        __half* Bs = Bsm + st * BS_H;
        // A: 128 rows x 64 halves = 1024 16B chunks
#pragma unroll
        for (int i = tid; i < 1024; i += 256) {
            const int m  = i >> 3;
            const int kq = (i & 7) * 8;
            CP_ASYNC16(smem_u32(As + m * APITCH + kq),
                       A + (long)(row0 + m) * lda + k0 + kq);
        }
        // B: 64 rows x 128 halves = 1024 16B chunks
#pragma unroll
        for (int i = tid; i < 1024; i += 256) {
            const int kk = i >> 4;
            const int nq = (i & 15) * 8;
            CP_ASYNC16(smem_u32(Bs + kk * BPITCH + nq),
                       B + (long)(k0 + kk) * ldb + col0 + nq);
        }
        CP_COMMIT();
    };

    const int KT = K / BK;
    load_stage(0, 0);
    if (KT > 1) load_stage(1, BK);

    int st = 0;
    for (int kt = 0; kt < KT; kt++) {
        if (kt + 1 < KT) { CP_WAIT(1); } else { CP_WAIT(0); }
        __syncthreads();            // all warps done with stage being overwritten below
        if (kt + 2 < KT) {
            int nst = st + 2; if (nst >= 3) nst -= 3;
            load_stage(nst, (kt + 2) * BK);
        }

        const __half* As = Asm + st * AS_H;
        const __half* Bs = Bsm + st * BS_H;
#pragma unroll
        for (int ks = 0; ks < BK; ks += 16) {
            unsigned af[2][4];
#pragma unroll
            for (int tm = 0; tm < 2; tm++) {
                const int r = warp_m0 + tm * 16 + (lane & 7) + ((lane >> 3) & 1) * 8;
                const int c = ks + (lane >> 4) * 8;
                LDSM_X4(af[tm][0], af[tm][1], af[tm][2], af[tm][3],
                        smem_u32(As + r * APITCH + c));
            }
            unsigned bf[8][2];
#pragma unroll
            for (int tn = 0; tn < 8; tn++) {
                const int r = ks + (lane & 15);
                const int c = warp_n0 + tn * 8;
                LDSM_X2_T(bf[tn][0], bf[tn][1], smem_u32(Bs + r * BPITCH + c));
            }
#pragma unroll
            for (int tm = 0; tm < 2; tm++)
#pragma unroll
                for (int tn = 0; tn < 8; tn++)
                    MMA16816(acc[tm][tn][0], acc[tm][tn][1], acc[tm][tn][2], acc[tm][tn][3],
                             af[tm][0], af[tm][1], af[tm][2], af[tm][3],
                             bf[tn][0], bf[tn][1]);
        }
        st++; if (st >= 3) st -= 3;
    }

    // epilogue
    __half* Ch = reinterpret_cast<__half*>(Cout);
    float*  Cf = reinterpret_cast<float*>(Cout);
#pragma unroll
    for (int tm = 0; tm < 2; tm++) {
#pragma unroll
        for (int tn = 0; tn < 8; tn++) {
            const int r = row0 + warp_m0 + tm * 16 + (lane >> 2);
            const int c = col0 + warp_n0 + tn * 8 + (lane & 3) * 2;
            float v[4] = {acc[tm][tn][0], acc[tm][tn][1], acc[tm][tn][2], acc[tm][tn][3]};
#pragma unroll
            for (int q = 0; q < 4; q++) v[q] *= alpha;
            if (bias) {
                const float b0 = bias[c], b1 = bias[c + 1];
                v[0] += b0; v[1] += b1; v[2] += b0; v[3] += b1;
            }
            if (GELU) {
#pragma unroll
                for (int q = 0; q < 4; q++)
                    v[q] = 0.5f * v[q] * (1.0f + erff(v[q] * 0.70710678118654752f));
            }
            if (RES) {
                v[0] += res[(long)r * ldc + c];
                v[1] += res[(long)r * ldc + c + 1];
                v[2] += res[(long)(r + 8) * ldc + c];
                v[3] += res[(long)(r + 8) * ldc + c + 1];
            }
            if (OUT_HALF) {
                *reinterpret_cast<__half2*>(Ch + (long)r * ldc + c)       = __floats2half2_rn(v[0], v[1]);
                *reinterpret_cast<__half2*>(Ch + (long)(r + 8) * ldc + c) = __floats2half2_rn(v[2], v[3]);
            } else {
                Cf[(long)r * ldc + c]           = v[0];
                Cf[(long)r * ldc + c + 1]       = v[1];
                Cf[(long)(r + 8) * ldc + c]     = v[2];
                Cf[(long)(r + 8) * ldc + c + 1] = v[3];
            }
        }
    }
}

// ---------------- launch ----------------
extern "C" void kernel_launch(void* const* d_in, const int* in_sizes, int n_in,
                              void* d_out, int out_size) {
    (void)in_sizes; (void)n_in; (void)out_size;
    const float* x     = (const float*)d_in[0];
    const float* ln1g  = (const float*)d_in[1];
    const float* ln1b  = (const float*)d_in[2];
    const float* ln2g  = (const float*)d_in[3];
    const float* ln2b  = (const float*)d_in[4];
    const float* wqkv  = (const float*)d_in[5];
    const float* bqkv  = (const float*)d_in[6];
    const float* wproj = (const float*)d_in[7];
    const float* bproj = (const float*)d_in[8];
    const float* wfc1  = (const float*)d_in[9];
    const float* bfc1  = (const float*)d_in[10];
    const float* wfc2  = (const float*)d_in[11];
    const float* bfc2  = (const float*)d_in[12];
    float* out = (float*)d_out;

    __half *h16, *qkv16, *y16, *ff16, *wqkv16, *wproj16, *wfc1_16, *wfc2_16;
    float *x1;
    cudaGetSymbolAddress((void**)&h16,     g_h16);
    cudaGetSymbolAddress((void**)&qkv16,   g_qkv16);
    cudaGetSymbolAddress((void**)&y16,     g_y16);
    cudaGetSymbolAddress((void**)&x1,      g_x1);
    cudaGetSymbolAddress((void**)&ff16,    g_ff16);
    cudaGetSymbolAddress((void**)&wqkv16,  g_wqkv16);
    cudaGetSymbolAddress((void**)&wproj16, g_wproj16);
    cudaGetSymbolAddress((void**)&wfc1_16, g_wfc1_16);
    cudaGetSymbolAddress((void**)&wfc2_16, g_wfc2_16);

    const long QKVROW = 3L * DMODEL;

    // dynamic smem: 3 * (128*72 + 64*136) halves = 107,520 bytes
    const int SM_BYTES = 3 * (128 * 72 + 64 * 136) * (int)sizeof(__half);
    cudaFuncSetAttribute(hgemm3_k<false, true,  false>, cudaFuncAttributeMaxDynamicSharedMemorySize, SM_BYTES);
    cudaFuncSetAttribute(hgemm3_k<false, false, true >, cudaFuncAttributeMaxDynamicSharedMemorySize, SM_BYTES);
    cudaFuncSetAttribute(hgemm3_k<true,  true,  false>, cudaFuncAttributeMaxDynamicSharedMemorySize, SM_BYTES);

    // 0) weight conversions
    {
        long n;
        n = (long)DMODEL * 3 * DMODEL; f2h_k<<<(unsigned)((n/4 + 255)/256), 256>>>(wqkv, wqkv16, n);
        n = (long)DMODEL * DMODEL;     f2h_k<<<(unsigned)((n/4 + 255)/256), 256>>>(wproj, wproj16, n);
        n = (long)DMODEL * FFDIM;      f2h_k<<<(unsigned)((n/4 + 255)/256), 256>>>(wfc1, wfc1_16, n);
        n = (long)FFDIM * DMODEL;      f2h_k<<<(unsigned)((n/4 + 255)/256), 256>>>(wfc2, wfc2_16, n);
    }

    // 1) h = LN1(x)
    ln_k<<<NROWS, 256>>>(x, ln1g, ln1b, h16);

    // 2) qkv = h @ w_qkv + b_qkv -> fp16
    hgemm3_k<false, true, false><<<dim3(3072/128, NROWS/128), 256, SM_BYTES>>>(
        h16, wqkv16, bqkv, nullptr, qkv16, DMODEL, DMODEL, QKVROW, QKVROW, 1.0f);

    // 3) fused attention -> y16
    flash_k<<<dim3(SEQ/128, 2 * NHEAD), 256>>>(qkv16, y16);

    // 4) x1 = x + y @ w_proj + b_proj (fp32)
    hgemm3_k<false, false, true><<<dim3(DMODEL/128, NROWS/128), 256, SM_BYTES>>>(
        y16, wproj16, bproj, x, x1, DMODEL, DMODEL, DMODEL, DMODEL, 1.0f);

    // 5) h = LN2(x1)
    ln_k<<<NROWS, 256>>>(x1, ln2g, ln2b, h16);

    // 6) ff = gelu(h @ w_fc1 + b_fc1) -> fp16
    hgemm3_k<true, true, false><<<dim3(FFDIM/128, NROWS/128), 256, SM_BYTES>>>(
        h16, wfc1_16, bfc1, nullptr, ff16, DMODEL, DMODEL, FFDIM, FFDIM, 1.0f);

    // 7) out = x1 + ff @ w_fc2 + b_fc2 (fp32)
    hgemm3_k<false, false, true><<<dim3(DMODEL/128, NROWS/128), 256, SM_BYTES>>>(
        ff16, wfc2_16, bfc2, x1, out, FFDIM, FFDIM, DMODEL, DMODEL, 1.0f);
}